// round 16
// baseline (speedup 1.0000x reference)
#include <cuda_runtime.h>
#include <cstdint>

#define L1D 4096
#define L2D 4096
#define NB 8
#define CC 3
#define TOT (NB * L2D)      // 32768 outputs per half
#define G 16
#define NC (G * G * G)      // 4096 cells
#define SLANES 8                         // lanes cooperating per query
#define QPWARP (32 / SLANES)             // 4 queries per warp
#define S_THREADS 256                    // 8 warps per CTA
#define QCH ((S_THREADS / 32) * QPWARP)  // 32 queries per CTA
#define QSPLIT (L2D / QCH)               // 128

// Binned refs per batch: (x, y, z, oidx-bits) + cell starts + work arrays.
__device__ float4         g_ref4[NB][L1D];
__device__ unsigned short g_cs[NB][NC + 1];
__device__ unsigned int   g_hist[NB][NC];
__device__ unsigned int   g_cur[NB][NC];

// Proven bit-exact XLA chain (rounds 8/10-15 passed, rel_err 0.0):
//   sr/sq = fl(fl(x*x + y*y) + z*z)     (mul/add, NO fma)
//   dot   = fma(qz,rz, fma(qy,ry, mul(qx,rx)))
//   d2    = fma(dot, -2, add(sq, sr))
static __device__ __forceinline__ float sumsq(float x, float y, float z) {
    return __fadd_rn(__fadd_rn(__fmul_rn(x, x), __fmul_rn(y, y)),
                     __fmul_rn(z, z));
}
static __device__ __forceinline__ float d2ref(float qx, float qy, float qz,
                                              float sq, float rx, float ry,
                                              float rz, float sr) {
    const float dot = __fmaf_rn(qz, rz, __fmaf_rn(qy, ry, __fmul_rn(qx, rx)));
    return __fmaf_rn(dot, -2.0f, __fadd_rn(sq, sr));
}
static __device__ __forceinline__ int cell_of(float x, float y, float z) {
    int cx = min(G - 1, max(0, (int)(x * (float)G)));
    int cy = min(G - 1, max(0, (int)(y * (float)G)));
    int cz = min(G - 1, max(0, (int)(z * (float)G)));
    return (cz * G + cy) * G + cx;
}

// ---- Binning pipeline: 4 wide kernels (was 1 kernel on 8 SMs) ----

// (a) zero the global histograms (required every graph replay).
__global__ __launch_bounds__(1024) void nn_zero() {
    const int i = blockIdx.x * 1024 + threadIdx.x;
    ((unsigned int*)g_hist)[i] = 0;  // grid sized exactly NB*NC/1024
}

// (b) histogram: 64 CTAs x 512 threads, one ref per thread, global atomics
// (spread addresses -> REDG-rate).
__global__ __launch_bounds__(512) void nn_hist(const float* __restrict__ c1) {
    const int b = blockIdx.x;
    const int n = b >> 3, chunk = b & 7;
    const int l = chunk * 512 + (int)threadIdx.x;
    const float* p = c1 + (size_t)l * (NB * CC) + n * CC;
    atomicAdd(&g_hist[n][cell_of(p[0], p[1], p[2])], 1u);
}

// (c) per-batch exclusive scan of 4096 counts -> cell starts + scatter cursors.
__global__ __launch_bounds__(1024) void nn_scan() {
    __shared__ unsigned int wsum[32];
    const int n = blockIdx.x;
    const int t = threadIdx.x;
    const int NPT = NC / 1024;  // 4
    unsigned int loc[NPT], s = 0;
#pragma unroll
    for (int j = 0; j < NPT; j++) { loc[j] = g_hist[n][t * NPT + j]; s += loc[j]; }
    unsigned int v = s;
#pragma unroll
    for (int o = 1; o < 32; o <<= 1) {
        unsigned int u = __shfl_up_sync(0xffffffffu, v, o);
        if ((t & 31) >= o) v += u;
    }
    const unsigned int excl = v - s;
    if ((t & 31) == 31) wsum[t >> 5] = v;
    __syncthreads();
    if (t < 32) {
        unsigned int w = wsum[t], vv = w;
#pragma unroll
        for (int o = 1; o < 32; o <<= 1) {
            unsigned int u = __shfl_up_sync(0xffffffffu, vv, o);
            if (t >= o) vv += u;
        }
        wsum[t] = vv - w;
    }
    __syncthreads();
    unsigned int base = wsum[t >> 5] + excl;
#pragma unroll
    for (int j = 0; j < NPT; j++) {
        const int c = t * NPT + j;
        g_cs[n][c] = (unsigned short)base;
        g_cur[n][c] = base;
        base += loc[j];
    }
    if (t == 0) g_cs[n][NC] = (unsigned short)L1D;
}

// (d) scatter: 64 CTAs x 512, one ref per thread, cursor via global atomic.
// Scatter order nondeterministic; FINAL OUTPUT invariant (original-index
// tie-break in search makes argmin order-independent).
__global__ __launch_bounds__(512) void nn_scatter(const float* __restrict__ c1) {
    const int b = blockIdx.x;
    const int n = b >> 3, chunk = b & 7;
    const int l = chunk * 512 + (int)threadIdx.x;
    const float* p = c1 + (size_t)l * (NB * CC) + n * CC;
    const float x = p[0], y = p[1], z = p[2];
    const unsigned pos = atomicAdd(&g_cur[n][cell_of(x, y, z)], 1u);
    g_ref4[n][pos] = make_float4(x, y, z, __uint_as_float((unsigned)l));
}

// ---- Search ----

// Evaluate one candidate against running (m, mi). Ties resolve to the
// smaller ORIGINAL index => first-occurrence argmin, scatter-order invariant.
static __device__ __forceinline__ void eval_cand(
    float4 rv, float qx, float qy, float qz, float sq, float& m, unsigned& mi) {
    const float sr = sumsq(rv.x, rv.y, rv.z);
    const float d = d2ref(qx, qy, qz, sq, rv.x, rv.y, rv.z, sr);
    const unsigned oi = __float_as_uint(rv.w);
    if (d < m) { m = d; mi = oi; }
    else if (d == m && oi < mi) { mi = oi; }
}

// Scan a contiguous ref range with next-iteration prefetch (hides L1 lat).
static __device__ __forceinline__ void scan_range(
    const float4* __restrict__ pR, unsigned s, unsigned e,
    float qx, float qy, float qz, float sq, float& m, unsigned& mi) {
    if (s >= e) return;
    float4 rv = pR[s];
    for (unsigned i = s + 1;; i++) {
        const bool more = i < e;
        float4 nx;
        if (more) nx = pR[i];          // prefetch before consuming rv
        eval_cand(rv, qx, qy, qz, sq, m, mi);
        if (!more) break;
        rv = nx;
    }
}

// Strided scan (step SLANES) used to split one row across the group.
static __device__ __forceinline__ void scan_strided(
    const float4* __restrict__ pR, unsigned s, unsigned e,
    float qx, float qy, float qz, float sq, float& m, unsigned& mi) {
    for (unsigned i = s; i < e; i += SLANES)
        eval_cand(pR[i], qx, qy, qz, sq, m, mi);
}

// 3-step reduce of (m, mi) across the 8-lane group.
static __device__ __forceinline__ void red8(unsigned gmask, float& m, unsigned& mi) {
#pragma unroll
    for (int o = SLANES / 2; o; o >>= 1) {
        const float om = __shfl_xor_sync(gmask, m, o);
        const unsigned omi = __shfl_xor_sync(gmask, mi, o);
        if (om < m || (om == m && omi < mi)) { m = om; mi = omi; }
    }
}

// 8-LANE-PER-QUERY ring search over CONTIGUOUS X-ROWS. Zero SMEM.
// __launch_bounds__(256, 8) caps regs at 32 => 8 CTAs/SM => grid 1024 fits
// in ONE wave (capacity 148*8 = 1184), killing the 1.4-wave tail.
__global__ __launch_bounds__(S_THREADS, 8)
void nn_search(const float* __restrict__ c2, float* __restrict__ out) {
    const int qc = blockIdx.x;
    const int n  = blockIdx.y;
    const int t  = threadIdx.x;
    const int warp = t >> 5, lane = t & 31;
    const int g = lane >> 3, sub = lane & 7;
    const unsigned gmask = 0xFFu << (g * 8);
    const int ql  = warp * QPWARP + g;
    const int l2i = qc * QCH + ql;

    const float4* __restrict__ pR = &g_ref4[n][0];
    const unsigned short* __restrict__ pS = &g_cs[n][0];

    const float* p = c2 + (size_t)l2i * (NB * CC) + n * CC;  // 8-lane broadcast
    const float qx = p[0], qy = p[1], qz = p[2];
    const float sq = sumsq(qx, qy, qz);
    const int cx = min(G - 1, max(0, (int)(qx * (float)G)));
    const int cy = min(G - 1, max(0, (int)(qy * (float)G)));
    const int cz = min(G - 1, max(0, (int)(qz * (float)G)));

    float m = __int_as_float(0x7f800000);
    unsigned mi = 0xffffffffu;

    // ---- r = 1: rows 0..7 -> lane sub; row 8 (dz=+1,dy=+1) split ----
    {
        const int xlo = max(cx - 1, 0), xhi = min(cx + 1, G - 1);
        {
            const int dz = sub / 3 - 1, dy = sub % 3 - 1;   // rows 0..7
            const int z2 = cz + dz, y2 = cy + dy;
            if ((unsigned)z2 < G && (unsigned)y2 < G) {
                const int rowb = (z2 * G + y2) * G;
                const unsigned s = pS[rowb + xlo], e = pS[rowb + xhi + 1];
                scan_range(pR, s, e, qx, qy, qz, sq, m, mi);
            }
        }
        {
            const int z2 = cz + 1, y2 = cy + 1;             // row 8
            if ((unsigned)z2 < G && (unsigned)y2 < G) {
                const int rowb = (z2 * G + y2) * G;
                const unsigned s = pS[rowb + xlo], e = pS[rowb + xhi + 1];
                scan_strided(pR, s + sub, e, qx, qy, qz, sq, m, mi);
            }
        }
    }
    red8(gmask, m, mi);
    // Unexamined cells (Chebyshev > r) hold points with fl-d2 > (r*h)^2-1.2e-6;
    // margin 4e-6 => no bit-equal candidate outside the scanned region.
    const float h = 1.0f / (float)G;
    bool done = (m <= h * h * 0.999f - 4e-6f);

    if (!done) {
        // ---- r = 2: rescan full 5x5 rows x [cx-2..cx+2] (dups harmless) ----
        const int xlo = max(cx - 2, 0), xhi = min(cx + 2, G - 1);
#pragma unroll 4
        for (int j = sub; j < 25; j += SLANES) {
            const int dz = j / 5 - 2, dy = j % 5 - 2;
            const int z2 = cz + dz, y2 = cy + dy;
            if ((unsigned)z2 < G && (unsigned)y2 < G) {
                const int rowb = (z2 * G + y2) * G;
                const unsigned s = pS[rowb + xlo], e = pS[rowb + xhi + 1];
                scan_range(pR, s, e, qx, qy, qz, sq, m, mi);
            }
        }
        red8(gmask, m, mi);
        const float b2 = 2.0f * h;
        done = (m <= b2 * b2 * 0.999f - 4e-6f);

        if (!done) {  // exhaustive fallback (probability ~0, correctness only)
            scan_strided(pR, sub, L1D, qx, qy, qz, sq, m, mi);
            red8(gmask, m, mi);
        }
    }

    if (sub == 0) {
        const int o = l2i * NB + n;
        out[o] = (float)mi;        // cluster index (<= 4095, exact in fp32)
        out[TOT + o] = (float)n;   // batch index
    }
}

extern "C" void kernel_launch(void* const* d_in, const int* in_sizes, int n_in,
                              void* d_out, int out_size) {
    const float* c1 = (const float*)d_in[0];  // coords1 [L1, N, C]
    const float* c2 = (const float*)d_in[1];  // coords2 [L2, N, C]
    float* out = (float*)d_out;

    nn_zero<<<(NB * NC) / 1024, 1024>>>();
    nn_hist<<<NB * 8, 512>>>(c1);
    nn_scan<<<NB, 1024>>>();
    nn_scatter<<<NB * 8, 512>>>(c1);
    dim3 grid(QSPLIT, NB);
    nn_search<<<grid, S_THREADS>>>(c2, out);
}